// round 10
// baseline (speedup 1.0000x reference)
#include <cuda_runtime.h>
#include <math.h>
#include <stdint.h>

#define NB    2
#define LSEQ  2048
#define HEADS 16
#define HD    64
#define EMB   1024

// scratch (static device arrays: allocation-free)
__device__ float    g_qp[NB*HEADS*LSEQ*HD];
__device__ float    g_kp[NB*HEADS*LSEQ*HD];
__device__ float    g_vp[NB*HEADS*LSEQ*HD];
__device__ float    g_att[NB*LSEQ*EMB];
__device__ unsigned g_mb[NB*LSEQ*(LSEQ/32)];

// ---------------------------------------------------------------------------
// helpers
// ---------------------------------------------------------------------------
// round-to-nearest tf32 (b32 destination per PTX spec)
__device__ __forceinline__ uint32_t tf32bits(float x) {
    uint32_t r;
    asm("cvt.rna.tf32.f32 %0, %1;" : "=r"(r) : "f"(x));
    return r;
}
__device__ __forceinline__ float tf32r(float x) {
    return __uint_as_float(tf32bits(x));
}
__device__ __forceinline__ uint32_t tf32u(float x) { return tf32bits(x); }

// m16n8k8 tf32 tensor-core mma (baseline PTX, works on plain sm_100 target)
__device__ __forceinline__ void mma8(float c[4], const uint32_t a[4],
                                     uint32_t b0, uint32_t b1) {
    asm volatile(
        "mma.sync.aligned.m16n8k8.row.col.f32.tf32.tf32.f32 "
        "{%0,%1,%2,%3}, {%4,%5,%6,%7}, {%8,%9}, {%0,%1,%2,%3};"
        : "+f"(c[0]), "+f"(c[1]), "+f"(c[2]), "+f"(c[3])
        : "r"(a[0]), "r"(a[1]), "r"(a[2]), "r"(a[3]), "r"(b0), "r"(b1));
}

// fp32 CUDA-core smem swizzle (proj kernel)
__device__ __forceinline__ int swz(int e, int c) { return c ^ (((e >> 2) & 7) << 2); }

// ---------------------------------------------------------------------------
// Kernel 1: per-head projections (fp32 compute, RAW fp32 output - round-4 flow)
// ---------------------------------------------------------------------------
__global__ __launch_bounds__(256) void proj_kernel(
    const float* __restrict__ vals, const float* __restrict__ keys,
    const float* __restrict__ quer, const float* __restrict__ Wv,
    const float* __restrict__ Wk,   const float* __restrict__ Wq)
{
    __shared__ float At[64*64];
    __shared__ float Bt[64*64];
    const int l0  = blockIdx.x * 64;
    const int h   = blockIdx.y;
    const int n   = blockIdx.z;
    const int tid = threadIdx.x;
    const int tx  = tid & 15, ty = tid >> 4;
    const int e4  = tx * 4;

    const float* xsrc[3] = {quer, keys, vals};
    const float* wsrc[3] = {Wq, Wk, Wv};
    float* dst[3];
    dst[0] = g_qp; dst[1] = g_kp; dst[2] = g_vp;

    for (int t = 0; t < 3; ++t) {
        __syncthreads();
        const float* x = xsrc[t];
        const float* w = wsrc[t];
        #pragma unroll
        for (int rr = 0; rr < 64; rr += 16) {
            int r = rr + ty;
            float4 xv = *(const float4*)(x + (size_t)(n*LSEQ + l0 + r)*EMB + h*HD + e4);
            At[(e4+0)*64 + swz(e4+0, r)] = xv.x;
            At[(e4+1)*64 + swz(e4+1, r)] = xv.y;
            At[(e4+2)*64 + swz(e4+2, r)] = xv.z;
            At[(e4+3)*64 + swz(e4+3, r)] = xv.w;
            float4 wv = *(const float4*)(w + r*HD + e4);
            Bt[(e4+0)*64 + swz(e4+0, r)] = wv.x;
            Bt[(e4+1)*64 + swz(e4+1, r)] = wv.y;
            Bt[(e4+2)*64 + swz(e4+2, r)] = wv.z;
            Bt[(e4+3)*64 + swz(e4+3, r)] = wv.w;
        }
        __syncthreads();
        float c[4][4] = {};
        #pragma unroll 8
        for (int e = 0; e < 64; ++e) {
            float4 a4 = *(const float4*)&At[e*64 + swz(e, ty*4)];
            float4 b4 = *(const float4*)&Bt[e*64 + swz(e, tx*4)];
            float a[4] = {a4.x, a4.y, a4.z, a4.w};
            #pragma unroll
            for (int i = 0; i < 4; ++i) {
                c[i][0] = fmaf(a[i], b4.x, c[i][0]);
                c[i][1] = fmaf(a[i], b4.y, c[i][1]);
                c[i][2] = fmaf(a[i], b4.z, c[i][2]);
                c[i][3] = fmaf(a[i], b4.w, c[i][3]);
            }
        }
        float* o = dst[t] + ((size_t)(n*HEADS + h)*LSEQ + l0)*HD;
        #pragma unroll
        for (int i = 0; i < 4; ++i) {
            float4 ov = make_float4(c[i][0], c[i][1], c[i][2], c[i][3]);
            *(float4*)(o + (ty*4+i)*HD + tx*4) = ov;
        }
    }
}

// ---------------------------------------------------------------------------
// Kernel 2: pack mask bits
// ---------------------------------------------------------------------------
__global__ __launch_bounds__(256) void maskpack_kernel(const int* __restrict__ mask)
{
    const int row  = blockIdx.x;
    const int tid  = threadIdx.x;
    const int warp = tid >> 5, lane = tid & 31;
    const int* mrow = mask + (size_t)row * LSEQ;
    #pragma unroll
    for (int it = 0; it < 8; ++it) {
        int k = it*256 + warp*32 + lane;
        unsigned b = __ballot_sync(0xffffffffu, mrow[k] != 0);
        if (lane == 0) g_mb[(size_t)row*64 + it*8 + warp] = b;
    }
}

// ---------------------------------------------------------------------------
// Kernel 3: tensor-core flash attention - round-4 structure AND data flow:
// static smem, LDG + in-loop tf32 cvt + STS fill, Q loaded with cvt,
// epilogue writes raw fp32.
// smK stride 68 / smV stride 72 -> conflict-free B-frag LDS.
// ---------------------------------------------------------------------------
#define KSTR 68
#define VSTR 72

__global__ __launch_bounds__(256) void attn_mma_kernel()
{
    __shared__ float smK[64*KSTR];
    __shared__ float smV[64*VSTR];
    const uint32_t* smKu = (const uint32_t*)smK;
    const uint32_t* smVu = (const uint32_t*)smV;

    const int q0   = blockIdx.x * 128;
    const int h    = blockIdx.y;
    const int n    = blockIdx.z;
    const int tid  = threadIdx.x;
    const int w    = tid >> 5;
    const int lane = tid & 31;
    const int g    = lane >> 2;      // row group within fragment
    const int t    = lane & 3;       // thread-in-group

    const size_t base = (size_t)(n*HEADS + h) * (LSEQ*HD);
    const float* Q = g_qp + base;
    const float* K = g_kp + base;
    const float* V = g_vp + base;

    // ---- Q fragments in registers (one-time scattered LDG, tf32-rounded)
    uint32_t Qa[8][4];
    {
        const float* Qr = Q + (size_t)(q0 + 16*w)*HD;
        #pragma unroll
        for (int s = 0; s < 8; ++s) {
            Qa[s][0] = tf32u(Qr[(size_t)g*HD     + 8*s + t]);
            Qa[s][1] = tf32u(Qr[(size_t)(g+8)*HD + 8*s + t]);
            Qa[s][2] = tf32u(Qr[(size_t)g*HD     + 8*s + t + 4]);
            Qa[s][3] = tf32u(Qr[(size_t)(g+8)*HD + 8*s + t + 4]);
        }
    }

    float O[8][4];
    #pragma unroll
    for (int j = 0; j < 8; ++j) { O[j][0]=0.f; O[j][1]=0.f; O[j][2]=0.f; O[j][3]=0.f; }
    float lsum_lo = 0.f, lsum_hi = 0.f;

    const int r0 = q0 + 16*w + g;
    const unsigned* mb0 = g_mb + (size_t)(n*LSEQ + r0) * 64;
    const unsigned* mb1 = mb0 + (size_t)8 * 64;   // row r0+8

    const int srcA = (lane & 28) | (t >> 1);
    const int srcB = srcA + 2;
    const bool sel = (t & 1);

    for (int kt = 0; kt < 32; ++kt) {
        __syncthreads();
        // ---- fill K/V tiles (tf32-rounded in-loop, round-4 style)
        {
            const float* Kp = K + (size_t)kt*64*HD;
            const float* Vp = V + (size_t)kt*64*HD;
            #pragma unroll
            for (int i = tid; i < 1024; i += 256) {
                int r = i >> 4, c = (i & 15) << 2;
                float4 kv = *(const float4*)(Kp + (size_t)r*HD + c);
                *(float4*)&smK[r*KSTR + c] =
                    make_float4(tf32r(kv.x), tf32r(kv.y), tf32r(kv.z), tf32r(kv.w));
                float4 vv = *(const float4*)(Vp + (size_t)r*HD + c);
                *(float4*)&smV[r*VSTR + c] =
                    make_float4(tf32r(vv.x), tf32r(vv.y), tf32r(vv.z), tf32r(vv.w));
            }
        }
        __syncthreads();

        // ---- S = Q K^T : 8 n-frags (64 keys) x 8 k-steps (d=64)
        float S[8][4];
        #pragma unroll
        for (int j = 0; j < 8; ++j) {
            S[j][0]=0.f; S[j][1]=0.f; S[j][2]=0.f; S[j][3]=0.f;
            const int kb = (8*j + g) * KSTR + t;
            #pragma unroll
            for (int s = 0; s < 8; ++s)
                mma8(S[j], Qa[s], smKu[kb + 8*s], smKu[kb + 8*s + 4]);
        }

        // ---- mask + exp (thread-local), P remap C-frag -> A-frag via shuffles
        const unsigned w0a = mb0[kt*2], w0b = mb0[kt*2 + 1];
        const unsigned w1a = mb1[kt*2], w1b = mb1[kt*2 + 1];
        uint32_t Pa[8][4];
        #pragma unroll
        for (int j = 0; j < 8; ++j) {
            const int cc = (8*j + 2*t) & 31;
            const unsigned wlo = (j < 4) ? w0a : w0b;
            const unsigned whi = (j < 4) ? w1a : w1b;
            float e0 = ((wlo >> cc)     & 1u) ? tf32r(__expf(S[j][0]*0.125f)) : 0.f;
            float e1 = ((wlo >> (cc+1)) & 1u) ? tf32r(__expf(S[j][1]*0.125f)) : 0.f;
            float e2 = ((whi >> cc)     & 1u) ? tf32r(__expf(S[j][2]*0.125f)) : 0.f;
            float e3 = ((whi >> (cc+1)) & 1u) ? tf32r(__expf(S[j][3]*0.125f)) : 0.f;
            lsum_lo += e0 + e1;
            lsum_hi += e2 + e3;
            float x0 = __shfl_sync(0xffffffffu, e0, srcA);
            float x1 = __shfl_sync(0xffffffffu, e1, srcA);
            Pa[j][0] = __float_as_uint(sel ? x1 : x0);
            float y0 = __shfl_sync(0xffffffffu, e2, srcA);
            float y1 = __shfl_sync(0xffffffffu, e3, srcA);
            Pa[j][1] = __float_as_uint(sel ? y1 : y0);
            x0 = __shfl_sync(0xffffffffu, e0, srcB);
            x1 = __shfl_sync(0xffffffffu, e1, srcB);
            Pa[j][2] = __float_as_uint(sel ? x1 : x0);
            y0 = __shfl_sync(0xffffffffu, e2, srcB);
            y1 = __shfl_sync(0xffffffffu, e3, srcB);
            Pa[j][3] = __float_as_uint(sel ? y1 : y0);
        }

        // ---- O += P @ V : 8 d-frags x 8 key-chunks
        #pragma unroll
        for (int j = 0; j < 8; ++j) {
            const int vb = 8*j + g + t*VSTR;
            #pragma unroll
            for (int s = 0; s < 8; ++s)
                mma8(O[j], Pa[s], smVu[vb + 8*s*VSTR], smVu[vb + (8*s+4)*VSTR]);
        }
    }

    // ---- normalize + write (raw fp32, round-4 flow)
    lsum_lo += __shfl_xor_sync(0xffffffffu, lsum_lo, 1);
    lsum_lo += __shfl_xor_sync(0xffffffffu, lsum_lo, 2);
    lsum_hi += __shfl_xor_sync(0xffffffffu, lsum_hi, 1);
    lsum_hi += __shfl_xor_sync(0xffffffffu, lsum_hi, 2);
    const float il = 1.f / lsum_lo;
    const float ih = 1.f / lsum_hi;

    float* o0 = g_att + (size_t)(n*LSEQ + r0)*EMB + h*HD;
    float* o1 = o0 + (size_t)8*EMB;
    #pragma unroll
    for (int j = 0; j < 8; ++j) {
        int c = 8*j + 2*t;
        *(float2*)&o0[c] = make_float2(O[j][0]*il, O[j][1]*il);
        *(float2*)&o1[c] = make_float2(O[j][2]*ih, O[j][3]*ih);
    }
}

// ---------------------------------------------------------------------------
// Kernel 4: out = att @ Wo^T + bo.  128x128 tile / block, K-chunk 32,
// in-kernel tf32 cvt (self-contained; reads raw g_att and raw Wo).
// Static smem: 2 x 128*36 floats = 36864 B -> 2 resident CTAs hide latency.
// ---------------------------------------------------------------------------
#define PSTR 36

__global__ __launch_bounds__(256) void outproj_mma_kernel(
    const float* __restrict__ Wo, const float* __restrict__ bo,
    float* __restrict__ out)
{
    __shared__ float smA[128*PSTR];
    __shared__ float smW[128*PSTR];
    const uint32_t* smAu = (const uint32_t*)smA;
    const uint32_t* smWu = (const uint32_t*)smW;

    const int o0   = blockIdx.x * 128;
    const int r0b  = blockIdx.y * 128;
    const int tid  = threadIdx.x;
    const int w    = tid >> 5;
    const int lane = tid & 31;
    const int wm   = w >> 1;        // 0..3  (32-row slice)
    const int wn   = w & 1;         // 0..1  (64-col slice)
    const int g    = lane >> 2;
    const int t    = lane & 3;

    float C[2][8][4];
    #pragma unroll
    for (int m = 0; m < 2; ++m)
        #pragma unroll
        for (int j = 0; j < 8; ++j) { C[m][j][0]=0.f; C[m][j][1]=0.f; C[m][j][2]=0.f; C[m][j][3]=0.f; }

    for (int ch = 0; ch < 32; ++ch) {
        __syncthreads();
        #pragma unroll
        for (int i = tid; i < 1024; i += 256) {
            int r = i >> 3, c = (i & 7) << 2;
            float4 av = *(const float4*)(g_att + (size_t)(r0b + r)*EMB + ch*32 + c);
            *(float4*)&smA[r*PSTR + c] =
                make_float4(tf32r(av.x), tf32r(av.y), tf32r(av.z), tf32r(av.w));
            float4 wv = *(const float4*)(Wo + (size_t)(o0 + r)*EMB + ch*32 + c);
            *(float4*)&smW[r*PSTR + c] =
                make_float4(tf32r(wv.x), tf32r(wv.y), tf32r(wv.z), tf32r(wv.w));
        }
        __syncthreads();

        const int ab0 = (32*wm      + g) * PSTR + t;
        const int ab1 = (32*wm + 16 + g) * PSTR + t;
        #pragma unroll
        for (int s = 0; s < 4; ++s) {
            uint32_t Aa0[4], Aa1[4];
            Aa0[0] = smAu[ab0 + 8*s];
            Aa0[1] = smAu[ab0 + 8*PSTR + 8*s];
            Aa0[2] = smAu[ab0 + 8*s + 4];
            Aa0[3] = smAu[ab0 + 8*PSTR + 8*s + 4];
            Aa1[0] = smAu[ab1 + 8*s];
            Aa1[1] = smAu[ab1 + 8*PSTR + 8*s];
            Aa1[2] = smAu[ab1 + 8*s + 4];
            Aa1[3] = smAu[ab1 + 8*PSTR + 8*s + 4];
            #pragma unroll
            for (int j = 0; j < 8; ++j) {
                const int wb = (64*wn + 8*j + g) * PSTR + t;
                uint32_t b0 = smWu[wb + 8*s], b1 = smWu[wb + 8*s + 4];
                mma8(C[0][j], Aa0, b0, b1);
                mma8(C[1][j], Aa1, b0, b1);
            }
        }
    }

    #pragma unroll
    for (int m = 0; m < 2; ++m) {
        const int row0 = r0b + 32*wm + 16*m + g;
        #pragma unroll
        for (int j = 0; j < 8; ++j) {
            int col = o0 + 64*wn + 8*j + 2*t;
            float2 bb = *(const float2*)&bo[col];
            *(float2*)&out[(size_t)row0*EMB + col] =
                make_float2(C[m][j][0] + bb.x, C[m][j][1] + bb.y);
            *(float2*)&out[(size_t)(row0+8)*EMB + col] =
                make_float2(C[m][j][2] + bb.x, C[m][j][3] + bb.y);
        }
    }
}

// ---------------------------------------------------------------------------
extern "C" void kernel_launch(void* const* d_in, const int* in_sizes, int n_in,
                              void* d_out, int out_size)
{
    (void)in_sizes; (void)n_in; (void)out_size;
    const float* vals = (const float*)d_in[0];
    const float* keys = (const float*)d_in[1];
    const float* quer = (const float*)d_in[2];
    const int*   mask = (const int*)  d_in[3];
    const float* Wv   = (const float*)d_in[4];
    const float* Wk   = (const float*)d_in[5];
    const float* Wq   = (const float*)d_in[6];
    const float* Wo   = (const float*)d_in[7];
    const float* bo   = (const float*)d_in[8];
    float* out = (float*)d_out;

    proj_kernel      <<<dim3(LSEQ/64, HEADS, NB), 256>>>(vals, keys, quer, Wv, Wk, Wq);
    maskpack_kernel  <<<NB*LSEQ, 256>>>(mask);
    attn_mma_kernel  <<<dim3(LSEQ/128, HEADS, NB), 256>>>();
    outproj_mma_kernel<<<dim3(EMB/128, NB*LSEQ/128), 256>>>(Wo, bo, out);
}

// round 12
// speedup vs baseline: 2.5681x; 2.5681x over previous
#include <cuda_runtime.h>
#include <math.h>
#include <stdint.h>

#define NB    2
#define LSEQ  2048
#define HEADS 16
#define HD    64
#define EMB   1024

// scratch (static device arrays: allocation-free). fp16 stored as unsigned short.
__device__ unsigned short g_qph[NB*HEADS*LSEQ*HD];   // [n][h][l][d]
__device__ unsigned short g_kph[NB*HEADS*LSEQ*HD];   // [n][h][l][d]
__device__ unsigned short g_vpT[NB*HEADS*HD*LSEQ];   // [n][h][d][l]  (transposed)
__device__ unsigned short g_atth[NB*LSEQ*EMB];       // [n*l][e]
__device__ unsigned short g_woh[EMB*EMB];            // [o][e]
__device__ unsigned g_mb[NB*LSEQ*(LSEQ/32)];

// ---------------------------------------------------------------------------
// helpers
// ---------------------------------------------------------------------------
// pack two f32 into f16x2 (lo, hi), round-to-nearest
__device__ __forceinline__ uint32_t packh2(float lo, float hi) {
    uint32_t d;
    asm("cvt.rn.f16x2.f32 %0, %1, %2;" : "=r"(d) : "f"(hi), "f"(lo));
    return d;
}
__device__ __forceinline__ uint32_t smem_u32(const void* p) {
    uint32_t a;
    asm("{ .reg .u64 t; cvta.to.shared.u64 t, %1; cvt.u32.u64 %0, t; }" : "=r"(a) : "l"(p));
    return a;
}
__device__ __forceinline__ void cpasync16(uint32_t dst, const void* src) {
    asm volatile("cp.async.cg.shared.global [%0], [%1], 16;" :: "r"(dst), "l"(src));
}
#define CP_COMMIT() asm volatile("cp.async.commit_group;" ::: "memory")
#define CP_WAIT1()  asm volatile("cp.async.wait_group 1;" ::: "memory")

// m16n8k16 fp16 tensor-core mma, fp32 accumulate (baseline PTX, sm_80+)
__device__ __forceinline__ void mma16(float c[4], const uint32_t a[4],
                                      uint32_t b0, uint32_t b1) {
    asm volatile(
        "mma.sync.aligned.m16n8k16.row.col.f32.f16.f16.f32 "
        "{%0,%1,%2,%3}, {%4,%5,%6,%7}, {%8,%9}, {%0,%1,%2,%3};"
        : "+f"(c[0]), "+f"(c[1]), "+f"(c[2]), "+f"(c[3])
        : "r"(a[0]), "r"(a[1]), "r"(a[2]), "r"(a[3]), "r"(b0), "r"(b1));
}

// fp32 CUDA-core smem swizzle (proj kernel)
__device__ __forceinline__ int swz(int e, int c) { return c ^ (((e >> 2) & 7) << 2); }

// ---------------------------------------------------------------------------
// Kernel 1: per-head projections (fp32 compute, fp16 output; V transposed)
// ---------------------------------------------------------------------------
__global__ __launch_bounds__(256) void proj_kernel(
    const float* __restrict__ vals, const float* __restrict__ keys,
    const float* __restrict__ quer, const float* __restrict__ Wv,
    const float* __restrict__ Wk,   const float* __restrict__ Wq)
{
    __shared__ float At[64*64];
    __shared__ float Bt[64*64];
    const int l0  = blockIdx.x * 64;
    const int h   = blockIdx.y;
    const int n   = blockIdx.z;
    const int tid = threadIdx.x;
    const int tx  = tid & 15, ty = tid >> 4;
    const int e4  = tx * 4;

    const float* xsrc[3] = {quer, keys, vals};
    const float* wsrc[3] = {Wq, Wk, Wv};

    for (int t = 0; t < 3; ++t) {
        __syncthreads();
        const float* x = xsrc[t];
        const float* w = wsrc[t];
        #pragma unroll
        for (int rr = 0; rr < 64; rr += 16) {
            int r = rr + ty;
            float4 xv = *(const float4*)(x + (size_t)(n*LSEQ + l0 + r)*EMB + h*HD + e4);
            At[(e4+0)*64 + swz(e4+0, r)] = xv.x;
            At[(e4+1)*64 + swz(e4+1, r)] = xv.y;
            At[(e4+2)*64 + swz(e4+2, r)] = xv.z;
            At[(e4+3)*64 + swz(e4+3, r)] = xv.w;
            float4 wv = *(const float4*)(w + r*HD + e4);
            Bt[(e4+0)*64 + swz(e4+0, r)] = wv.x;
            Bt[(e4+1)*64 + swz(e4+1, r)] = wv.y;
            Bt[(e4+2)*64 + swz(e4+2, r)] = wv.z;
            Bt[(e4+3)*64 + swz(e4+3, r)] = wv.w;
        }
        __syncthreads();
        float c[4][4] = {};
        #pragma unroll 8
        for (int e = 0; e < 64; ++e) {
            float4 a4 = *(const float4*)&At[e*64 + swz(e, ty*4)];
            float4 b4 = *(const float4*)&Bt[e*64 + swz(e, tx*4)];
            float a[4] = {a4.x, a4.y, a4.z, a4.w};
            #pragma unroll
            for (int i = 0; i < 4; ++i) {
                c[i][0] = fmaf(a[i], b4.x, c[i][0]);
                c[i][1] = fmaf(a[i], b4.y, c[i][1]);
                c[i][2] = fmaf(a[i], b4.z, c[i][2]);
                c[i][3] = fmaf(a[i], b4.w, c[i][3]);
            }
        }
        const size_t nh = (size_t)(n*HEADS + h);
        if (t == 2) {
            // V: write transposed [d][l]
            unsigned short* vT = g_vpT + nh*HD*LSEQ;
            #pragma unroll
            for (int j = 0; j < 4; ++j) {
                uint2 pv;
                pv.x = packh2(c[0][j], c[1][j]);
                pv.y = packh2(c[2][j], c[3][j]);
                *(uint2*)&vT[(size_t)(tx*4 + j)*LSEQ + l0 + ty*4] = pv;
            }
        } else {
            unsigned short* o = (t == 0 ? g_qph : g_kph) + (nh*LSEQ + l0)*HD;
            #pragma unroll
            for (int i = 0; i < 4; ++i) {
                uint2 pv;
                pv.x = packh2(c[i][0], c[i][1]);
                pv.y = packh2(c[i][2], c[i][3]);
                *(uint2*)&o[(size_t)(ty*4+i)*HD + tx*4] = pv;
            }
        }
    }
}

// ---------------------------------------------------------------------------
// Kernel 2: pack mask bits
// ---------------------------------------------------------------------------
__global__ __launch_bounds__(256) void maskpack_kernel(const int* __restrict__ mask)
{
    const int row  = blockIdx.x;
    const int tid  = threadIdx.x;
    const int warp = tid >> 5, lane = tid & 31;
    const int* mrow = mask + (size_t)row * LSEQ;
    #pragma unroll
    for (int it = 0; it < 8; ++it) {
        int k = it*256 + warp*32 + lane;
        unsigned b = __ballot_sync(0xffffffffu, mrow[k] != 0);
        if (lane == 0) g_mb[(size_t)row*64 + it*8 + warp] = b;
    }
}

// ---------------------------------------------------------------------------
// Kernel 2b: Wo -> fp16
// ---------------------------------------------------------------------------
__global__ __launch_bounds__(256) void wo_half_kernel(const float* __restrict__ Wo)
{
    const int i = (blockIdx.x * 256 + threadIdx.x) * 4;
    float4 v = *(const float4*)(Wo + i);
    uint2 pv;
    pv.x = packh2(v.x, v.y);
    pv.y = packh2(v.z, v.w);
    *(uint2*)&g_woh[i] = pv;
}

// ---------------------------------------------------------------------------
// Kernel 3: fp16 tensor-core flash attention.
// 256 thr = 8 warps; Q tile 128 rows, K tile 64 keys, m16n8k16 (half the mmas).
// K smem [key][d] stride 72 halves, V smem [d][key] stride 72 halves:
// B-frag 32-bit LDS word index = row*36 + 8c + t -> (4g+t) mod 32 conflict-free.
// P remap C->A frag is thread-local (fp16 layout), no shuffles.
// Double-buffered cp.async (raw fp16 copies). Static smem 36 KB, 2 CTAs/SM.
// ---------------------------------------------------------------------------
#define SH 72

__global__ __launch_bounds__(256, 2) void attn_mma_kernel()
{
    __shared__ unsigned short smK16[2][64*SH];
    __shared__ unsigned short smV16[2][64*SH];

    const int q0   = blockIdx.x * 128;
    const int h    = blockIdx.y;
    const int n    = blockIdx.z;
    const int tid  = threadIdx.x;
    const int w    = tid >> 5;
    const int lane = tid & 31;
    const int g    = lane >> 2;
    const int t    = lane & 3;

    const size_t nh = (size_t)(n*HEADS + h);
    const unsigned short* Kp = g_kph + nh*LSEQ*HD;   // [l][d]
    const unsigned short* Vp = g_vpT + nh*HD*LSEQ;   // [d][l]

    // ---- Q fragments (m16n8k16 A): 4 k-chunks x 4 regs, 32-bit loads
    uint32_t Qa[4][4];
    {
        const uint32_t* Qr = (const uint32_t*)(g_qph + (nh*LSEQ + q0 + 16*w)*HD);
        #pragma unroll
        for (int c = 0; c < 4; ++c) {
            Qa[c][0] = Qr[g*32     + 8*c + t];
            Qa[c][1] = Qr[(g+8)*32 + 8*c + t];
            Qa[c][2] = Qr[g*32     + 8*c + t + 4];
            Qa[c][3] = Qr[(g+8)*32 + 8*c + t + 4];
        }
    }

    float O[8][4];
    #pragma unroll
    for (int j = 0; j < 8; ++j) { O[j][0]=0.f; O[j][1]=0.f; O[j][2]=0.f; O[j][3]=0.f; }
    float lsum_lo = 0.f, lsum_hi = 0.f;

    const int r0 = q0 + 16*w + g;
    const unsigned* mb0 = g_mb + (size_t)(n*LSEQ + r0) * 64;
    const unsigned* mb1 = mb0 + (size_t)8 * 64;

    auto prefetch = [&](int kt, int b) {
        const unsigned short* Ks = Kp + (size_t)(kt*64)*HD;
        const unsigned short* Vs = Vp + kt*64;
        #pragma unroll
        for (int i = tid; i < 512; i += 256) {
            int r = i >> 3, c8 = (i & 7) << 3;
            cpasync16(smem_u32(&smK16[b][r*SH + c8]), Ks + (size_t)r*HD + c8);
            cpasync16(smem_u32(&smV16[b][r*SH + c8]), Vs + (size_t)r*LSEQ + c8);
        }
    };

    prefetch(0, 0);
    CP_COMMIT();

    for (int kt = 0; kt < 32; ++kt) {
        const int b = kt & 1;
        __syncthreads();
        prefetch((kt + 1) & 31, b ^ 1);
        CP_COMMIT();
        CP_WAIT1();
        __syncthreads();

        const uint32_t* Ku = (const uint32_t*)smK16[b];
        const uint32_t* Vu = (const uint32_t*)smV16[b];

        // ---- S = Q K^T : 8 n-frags x 4 k16-chunks
        float S[8][4];
        #pragma unroll
        for (int j = 0; j < 8; ++j) {
            S[j][0]=0.f; S[j][1]=0.f; S[j][2]=0.f; S[j][3]=0.f;
            const int kb = (8*j + g)*36 + t;
            #pragma unroll
            for (int c = 0; c < 4; ++c)
                mma16(S[j], Qa[c], Ku[kb + 8*c], Ku[kb + 8*c + 4]);
        }

        // ---- mask + exp; P packs directly into fp16 A-frags (thread-local)
        const unsigned w0a = mb0[kt*2], w0b = mb0[kt*2 + 1];
        const unsigned w1a = mb1[kt*2], w1b = mb1[kt*2 + 1];
        uint32_t Pa[4][4];
        #pragma unroll
        for (int j = 0; j < 8; ++j) {
            const int cc = (8*j + 2*t) & 31;
            const unsigned wlo = (j < 4) ? w0a : w0b;
            const unsigned whi = (j < 4) ? w1a : w1b;
            float e0 = ((wlo >> cc)     & 1u) ? __expf(S[j][0]*0.125f) : 0.f;
            float e1 = ((wlo >> (cc+1)) & 1u) ? __expf(S[j][1]*0.125f) : 0.f;
            float e2 = ((whi >> cc)     & 1u) ? __expf(S[j][2]*0.125f) : 0.f;
            float e3 = ((whi >> (cc+1)) & 1u) ? __expf(S[j][3]*0.125f) : 0.f;
            lsum_lo += e0 + e1;
            lsum_hi += e2 + e3;
            Pa[j >> 1][(j & 1)*2 + 0] = packh2(e0, e1);
            Pa[j >> 1][(j & 1)*2 + 1] = packh2(e2, e3);
        }

        // ---- O += P @ V : 8 d-frags x 4 key16-chunks
        #pragma unroll
        for (int j = 0; j < 8; ++j) {
            const int vb = (8*j + g)*36 + t;
            #pragma unroll
            for (int c = 0; c < 4; ++c)
                mma16(O[j], Pa[c], Vu[vb + 8*c], Vu[vb + 8*c + 4]);
        }
    }

    // ---- normalize + write fp16
    lsum_lo += __shfl_xor_sync(0xffffffffu, lsum_lo, 1);
    lsum_lo += __shfl_xor_sync(0xffffffffu, lsum_lo, 2);
    lsum_hi += __shfl_xor_sync(0xffffffffu, lsum_hi, 1);
    lsum_hi += __shfl_xor_sync(0xffffffffu, lsum_hi, 2);
    const float il = 1.f / lsum_lo;
    const float ih = 1.f / lsum_hi;

    uint32_t* o0 = (uint32_t*)g_atth + (size_t)(n*LSEQ + r0)*(EMB/2) + h*(HD/2);
    uint32_t* o1 = o0 + (size_t)8*(EMB/2);
    #pragma unroll
    for (int j = 0; j < 8; ++j) {
        o0[4*j + t] = packh2(O[j][0]*il, O[j][1]*il);
        o1[4*j + t] = packh2(O[j][2]*ih, O[j][3]*ih);
    }
}

// ---------------------------------------------------------------------------
// Kernel 4: out = att @ Wo^T + bo, fp16 mma, 128x128 tile, K-chunk 64,
// double-buffered cp.async from g_atth / g_woh. Dynamic smem 73728 B.
// ---------------------------------------------------------------------------
#define OPBUFH 18432   // halves per stage (A 9216 + W 9216)

__global__ __launch_bounds__(256) void outproj_mma_kernel(
    const float* __restrict__ bo, float* __restrict__ out)
{
    extern __shared__ unsigned short dsm16[];

    const int o0   = blockIdx.x * 128;
    const int r0b  = blockIdx.y * 128;
    const int tid  = threadIdx.x;
    const int w    = tid >> 5;
    const int lane = tid & 31;
    const int wm   = w >> 1;        // 0..3 (32-row slice)
    const int wn   = w & 1;         // 0..1 (64-col slice)
    const int g    = lane >> 2;
    const int t    = lane & 3;

    auto prefetch = [&](int ch, int b) {
        unsigned short* Ab = dsm16 + b*OPBUFH;
        unsigned short* Wb = Ab + 9216;
        #pragma unroll
        for (int i = tid; i < 1024; i += 256) {
            int r = i >> 3, c8 = (i & 7) << 3;
            cpasync16(smem_u32(&Ab[r*SH + c8]),
                      g_atth + (size_t)(r0b + r)*EMB + ch*64 + c8);
            cpasync16(smem_u32(&Wb[r*SH + c8]),
                      g_woh + (size_t)(o0 + r)*EMB + ch*64 + c8);
        }
    };

    float C[2][8][4];
    #pragma unroll
    for (int m = 0; m < 2; ++m)
        #pragma unroll
        for (int j = 0; j < 8; ++j) { C[m][j][0]=0.f; C[m][j][1]=0.f; C[m][j][2]=0.f; C[m][j][3]=0.f; }

    prefetch(0, 0);
    CP_COMMIT();

    for (int ch = 0; ch < 16; ++ch) {
        const int b = ch & 1;
        __syncthreads();
        prefetch((ch + 1) & 15, b ^ 1);
        CP_COMMIT();
        CP_WAIT1();
        __syncthreads();

        const uint32_t* Au = (const uint32_t*)(dsm16 + b*OPBUFH);
        const uint32_t* Wu = Au + 4608;

        #pragma unroll
        for (int s = 0; s < 4; ++s) {
            uint32_t Aa0[4], Aa1[4];
            const int a0w = (32*wm      + g)*36 + 8*s + t;
            const int a1w = (32*wm + 16 + g)*36 + 8*s + t;
            Aa0[0] = Au[a0w];
            Aa0[1] = Au[a0w + 8*36];
            Aa0[2] = Au[a0w + 4];
            Aa0[3] = Au[a0w + 8*36 + 4];
            Aa1[0] = Au[a1w];
            Aa1[1] = Au[a1w + 8*36];
            Aa1[2] = Au[a1w + 4];
            Aa1[3] = Au[a1w + 8*36 + 4];
            #pragma unroll
            for (int j = 0; j < 8; ++j) {
                const int ww = (64*wn + 8*j + g)*36 + 8*s + t;
                uint32_t b0 = Wu[ww], b1 = Wu[ww + 4];
                mma16(C[0][j], Aa0, b0, b1);
                mma16(C[1][j], Aa1, b0, b1);
            }
        }
    }

    #pragma unroll
    for (int m = 0; m < 2; ++m) {
        const int row0 = r0b + 32*wm + 16*m + g;
        #pragma unroll
        for (int j = 0; j < 8; ++j) {
            int col = o0 + 64*wn + 8*j + 2*t;
            float2 bb = *(const float2*)&bo[col];
            *(float2*)&out[(size_t)row0*EMB + col] =
                make_float2(C[m][j][0] + bb.x, C[m][j][1] + bb.y);
            *(float2*)&out[(size_t)(row0+8)*EMB + col] =
                make_float2(C[m][j][2] + bb.x, C[m][j][3] + bb.y);
        }
    }
}

// ---------------------------------------------------------------------------
extern "C" void kernel_launch(void* const* d_in, const int* in_sizes, int n_in,
                              void* d_out, int out_size)
{
    (void)in_sizes; (void)n_in; (void)out_size;
    const float* vals = (const float*)d_in[0];
    const float* keys = (const float*)d_in[1];
    const float* quer = (const float*)d_in[2];
    const int*   mask = (const int*)  d_in[3];
    const float* Wv   = (const float*)d_in[4];
    const float* Wk   = (const float*)d_in[5];
    const float* Wq   = (const float*)d_in[6];
    const float* Wo   = (const float*)d_in[7];
    const float* bo   = (const float*)d_in[8];
    float* out = (float*)d_out;

    cudaFuncSetAttribute(outproj_mma_kernel,
                         cudaFuncAttributeMaxDynamicSharedMemorySize, 2*OPBUFH*2);

    proj_kernel      <<<dim3(LSEQ/64, HEADS, NB), 256>>>(vals, keys, quer, Wv, Wk, Wq);
    maskpack_kernel  <<<NB*LSEQ, 256>>>(mask);
    wo_half_kernel   <<<EMB*EMB/1024, 256>>>(Wo);
    attn_mma_kernel  <<<dim3(LSEQ/128, HEADS, NB), 256>>>();
    outproj_mma_kernel<<<dim3(EMB/128, NB*LSEQ/128), 256, 2*OPBUFH*2>>>(bo, out);
}

// round 13
// speedup vs baseline: 2.7675x; 1.0776x over previous
#include <cuda_runtime.h>
#include <math.h>
#include <stdint.h>

#define NB    2
#define LSEQ  2048
#define HEADS 16
#define HD    64
#define EMB   1024

// scratch (static device arrays: allocation-free). fp16 stored as unsigned short.
__device__ unsigned short g_qph[NB*HEADS*LSEQ*HD];   // [n][h][l][d]  (pre-scaled by 0.125*log2e)
__device__ unsigned short g_kph[NB*HEADS*LSEQ*HD];   // [n][h][l][d]
__device__ unsigned short g_vpT[NB*HEADS*HD*LSEQ];   // [n][h][d][l]  (transposed)
__device__ unsigned short g_atth[NB*LSEQ*EMB];       // [n*l][e]
__device__ unsigned short g_woh[EMB*EMB];            // [o][e]
__device__ unsigned g_mb[NB*LSEQ*(LSEQ/32)];

// ---------------------------------------------------------------------------
// helpers
// ---------------------------------------------------------------------------
__device__ __forceinline__ uint32_t packh2(float lo, float hi) {
    uint32_t d;
    asm("cvt.rn.f16x2.f32 %0, %1, %2;" : "=r"(d) : "f"(hi), "f"(lo));
    return d;
}
__device__ __forceinline__ float ex2f(float x) {   // 2^x via MUFU
    float r;
    asm("ex2.approx.ftz.f32 %0, %1;" : "=f"(r) : "f"(x));
    return r;
}
__device__ __forceinline__ uint32_t smem_u32(const void* p) {
    uint32_t a;
    asm("{ .reg .u64 t; cvta.to.shared.u64 t, %1; cvt.u32.u64 %0, t; }" : "=r"(a) : "l"(p));
    return a;
}
__device__ __forceinline__ void cpasync16(uint32_t dst, const void* src) {
    asm volatile("cp.async.cg.shared.global [%0], [%1], 16;" :: "r"(dst), "l"(src));
}
#define CP_COMMIT() asm volatile("cp.async.commit_group;" ::: "memory")
#define CP_WAIT1()  asm volatile("cp.async.wait_group 1;" ::: "memory")

// ldmatrix x4: 4 8x8 fp16 tiles; lanes 0-7/8-15/16-23/24-31 give row addrs of tiles 0-3
#define LDSM_X4(r0, r1, r2, r3, addr)                                          \
    asm volatile("ldmatrix.sync.aligned.m8n8.x4.shared.b16 {%0,%1,%2,%3}, [%4];" \
        : "=r"(r0), "=r"(r1), "=r"(r2), "=r"(r3) : "r"(addr))

// m16n8k16 fp16 tensor-core mma, fp32 accumulate (baseline PTX, sm_80+)
__device__ __forceinline__ void mma16(float c[4], const uint32_t a[4],
                                      uint32_t b0, uint32_t b1) {
    asm volatile(
        "mma.sync.aligned.m16n8k16.row.col.f32.f16.f16.f32 "
        "{%0,%1,%2,%3}, {%4,%5,%6,%7}, {%8,%9}, {%0,%1,%2,%3};"
        : "+f"(c[0]), "+f"(c[1]), "+f"(c[2]), "+f"(c[3])
        : "r"(a[0]), "r"(a[1]), "r"(a[2]), "r"(a[3]), "r"(b0), "r"(b1));
}

// fp32 CUDA-core smem swizzle (proj kernel)
__device__ __forceinline__ int swz(int e, int c) { return c ^ (((e >> 2) & 7) << 2); }

// softmax scale folded into Q: 0.125 * log2(e)
#define QSCALE 0.1803368801111204f

// ---------------------------------------------------------------------------
// Kernel 1: per-head projections (fp32 compute, fp16 output; V transposed;
// Q pre-scaled by QSCALE so attention's exp is a bare ex2)
// ---------------------------------------------------------------------------
__global__ __launch_bounds__(256) void proj_kernel(
    const float* __restrict__ vals, const float* __restrict__ keys,
    const float* __restrict__ quer, const float* __restrict__ Wv,
    const float* __restrict__ Wk,   const float* __restrict__ Wq)
{
    __shared__ float At[64*64];
    __shared__ float Bt[64*64];
    const int l0  = blockIdx.x * 64;
    const int h   = blockIdx.y;
    const int n   = blockIdx.z;
    const int tid = threadIdx.x;
    const int tx  = tid & 15, ty = tid >> 4;
    const int e4  = tx * 4;

    const float* xsrc[3] = {quer, keys, vals};
    const float* wsrc[3] = {Wq, Wk, Wv};

    for (int t = 0; t < 3; ++t) {
        __syncthreads();
        const float* x = xsrc[t];
        const float* w = wsrc[t];
        #pragma unroll
        for (int rr = 0; rr < 64; rr += 16) {
            int r = rr + ty;
            float4 xv = *(const float4*)(x + (size_t)(n*LSEQ + l0 + r)*EMB + h*HD + e4);
            At[(e4+0)*64 + swz(e4+0, r)] = xv.x;
            At[(e4+1)*64 + swz(e4+1, r)] = xv.y;
            At[(e4+2)*64 + swz(e4+2, r)] = xv.z;
            At[(e4+3)*64 + swz(e4+3, r)] = xv.w;
            float4 wv = *(const float4*)(w + r*HD + e4);
            Bt[(e4+0)*64 + swz(e4+0, r)] = wv.x;
            Bt[(e4+1)*64 + swz(e4+1, r)] = wv.y;
            Bt[(e4+2)*64 + swz(e4+2, r)] = wv.z;
            Bt[(e4+3)*64 + swz(e4+3, r)] = wv.w;
        }
        __syncthreads();
        float c[4][4] = {};
        #pragma unroll 8
        for (int e = 0; e < 64; ++e) {
            float4 a4 = *(const float4*)&At[e*64 + swz(e, ty*4)];
            float4 b4 = *(const float4*)&Bt[e*64 + swz(e, tx*4)];
            float a[4] = {a4.x, a4.y, a4.z, a4.w};
            #pragma unroll
            for (int i = 0; i < 4; ++i) {
                c[i][0] = fmaf(a[i], b4.x, c[i][0]);
                c[i][1] = fmaf(a[i], b4.y, c[i][1]);
                c[i][2] = fmaf(a[i], b4.z, c[i][2]);
                c[i][3] = fmaf(a[i], b4.w, c[i][3]);
            }
        }
        const size_t nh = (size_t)(n*HEADS + h);
        if (t == 2) {
            // V: write transposed [d][l]
            unsigned short* vT = g_vpT + nh*HD*LSEQ;
            #pragma unroll
            for (int j = 0; j < 4; ++j) {
                uint2 pv;
                pv.x = packh2(c[0][j], c[1][j]);
                pv.y = packh2(c[2][j], c[3][j]);
                *(uint2*)&vT[(size_t)(tx*4 + j)*LSEQ + l0 + ty*4] = pv;
            }
        } else {
            const float sc = (t == 0) ? QSCALE : 1.0f;
            unsigned short* o = (t == 0 ? g_qph : g_kph) + (nh*LSEQ + l0)*HD;
            #pragma unroll
            for (int i = 0; i < 4; ++i) {
                uint2 pv;
                pv.x = packh2(c[i][0]*sc, c[i][1]*sc);
                pv.y = packh2(c[i][2]*sc, c[i][3]*sc);
                *(uint2*)&o[(size_t)(ty*4+i)*HD + tx*4] = pv;
            }
        }
    }
}

// ---------------------------------------------------------------------------
// Kernel 2: pack mask bits
// ---------------------------------------------------------------------------
__global__ __launch_bounds__(256) void maskpack_kernel(const int* __restrict__ mask)
{
    const int row  = blockIdx.x;
    const int tid  = threadIdx.x;
    const int warp = tid >> 5, lane = tid & 31;
    const int* mrow = mask + (size_t)row * LSEQ;
    #pragma unroll
    for (int it = 0; it < 8; ++it) {
        int k = it*256 + warp*32 + lane;
        unsigned b = __ballot_sync(0xffffffffu, mrow[k] != 0);
        if (lane == 0) g_mb[(size_t)row*64 + it*8 + warp] = b;
    }
}

// ---------------------------------------------------------------------------
// Kernel 2b: Wo -> fp16
// ---------------------------------------------------------------------------
__global__ __launch_bounds__(256) void wo_half_kernel(const float* __restrict__ Wo)
{
    const int i = (blockIdx.x * 256 + threadIdx.x) * 4;
    float4 v = *(const float4*)(Wo + i);
    uint2 pv;
    pv.x = packh2(v.x, v.y);
    pv.y = packh2(v.z, v.w);
    *(uint2*)&g_woh[i] = pv;
}

// ---------------------------------------------------------------------------
// Kernel 3: fp16 tensor-core flash attention.
// B-fragments loaded with ldmatrix.x4 (4x fewer smem instructions).
// exp is bare ex2 (scale folded into Q). Mask words pre-shifted per tile.
// Double-buffered cp.async, static smem 36 KB, 2 CTAs/SM.
// ---------------------------------------------------------------------------
#define SH 72

__global__ __launch_bounds__(256, 2) void attn_mma_kernel()
{
    __shared__ unsigned short smK16[2][64*SH];
    __shared__ unsigned short smV16[2][64*SH];

    const int q0   = blockIdx.x * 128;
    const int h    = blockIdx.y;
    const int n    = blockIdx.z;
    const int tid  = threadIdx.x;
    const int w    = tid >> 5;
    const int lane = tid & 31;
    const int g    = lane >> 2;
    const int t    = lane & 3;
    const int m4   = lane >> 3;      // ldmatrix: matrix index 0..3
    const int r8   = lane & 7;       // ldmatrix: row within matrix

    const size_t nh = (size_t)(n*HEADS + h);
    const unsigned short* Kp = g_kph + nh*LSEQ*HD;   // [l][d]
    const unsigned short* Vp = g_vpT + nh*HD*LSEQ;   // [d][l]

    // per-thread ldmatrix byte offset within a tile buffer:
    //   addr(j, cpair) = base + tconst + j*(16*SH) + cpair*64
    const uint32_t tconst = (uint32_t)(r8*SH + 16*(m4 >> 1) + 8*(m4 & 1)) * 2;

    // ---- Q fragments (m16n8k16 A): 4 k-chunks x 4 regs, 32-bit loads
    uint32_t Qa[4][4];
    {
        const uint32_t* Qr = (const uint32_t*)(g_qph + (nh*LSEQ + q0 + 16*w)*HD);
        #pragma unroll
        for (int c = 0; c < 4; ++c) {
            Qa[c][0] = Qr[g*32     + 8*c + t];
            Qa[c][1] = Qr[(g+8)*32 + 8*c + t];
            Qa[c][2] = Qr[g*32     + 8*c + t + 4];
            Qa[c][3] = Qr[(g+8)*32 + 8*c + t + 4];
        }
    }

    float O[8][4];
    #pragma unroll
    for (int j = 0; j < 8; ++j) { O[j][0]=0.f; O[j][1]=0.f; O[j][2]=0.f; O[j][3]=0.f; }
    float lsum_lo = 0.f, lsum_hi = 0.f;

    const int r0 = q0 + 16*w + g;
    const unsigned* mb0 = g_mb + (size_t)(n*LSEQ + r0) * 64;
    const unsigned* mb1 = mb0 + (size_t)8 * 64;

    auto prefetch = [&](int kt, int b) {
        const unsigned short* Ks = Kp + (size_t)(kt*64)*HD;
        const unsigned short* Vs = Vp + kt*64;
        #pragma unroll
        for (int i = tid; i < 512; i += 256) {
            int r = i >> 3, c8 = (i & 7) << 3;
            cpasync16(smem_u32(&smK16[b][r*SH + c8]), Ks + (size_t)r*HD + c8);
            cpasync16(smem_u32(&smV16[b][r*SH + c8]), Vs + (size_t)r*LSEQ + c8);
        }
    };

    prefetch(0, 0);
    CP_COMMIT();

    for (int kt = 0; kt < 32; ++kt) {
        const int b = kt & 1;
        __syncthreads();
        prefetch((kt + 1) & 31, b ^ 1);
        CP_COMMIT();
        CP_WAIT1();
        __syncthreads();

        const uint32_t kaddr = smem_u32(&smK16[b][0]) + tconst;
        const uint32_t vaddr = smem_u32(&smV16[b][0]) + tconst;

        // ---- S = Q K^T : 8 n-frags, B-frags via 2 ldmatrix.x4 per frag
        float S[8][4];
        #pragma unroll
        for (int j = 0; j < 8; ++j) {
            S[j][0]=0.f; S[j][1]=0.f; S[j][2]=0.f; S[j][3]=0.f;
            uint32_t a0 = kaddr + j*(16*SH);
            uint32_t b0, b1, b2, b3, b4, b5, b6, b7;
            LDSM_X4(b0, b1, b2, b3, a0);
            LDSM_X4(b4, b5, b6, b7, a0 + 64);
            mma16(S[j], Qa[0], b0, b1);
            mma16(S[j], Qa[1], b2, b3);
            mma16(S[j], Qa[2], b4, b5);
            mma16(S[j], Qa[3], b6, b7);
        }

        // ---- mask + ex2; P packs directly into fp16 A-frags (thread-local)
        const unsigned ua = mb0[kt*2]     >> (2*t);
        const unsigned ub = mb0[kt*2 + 1] >> (2*t);
        const unsigned va = mb1[kt*2]     >> (2*t);
        const unsigned vb = mb1[kt*2 + 1] >> (2*t);
        uint32_t Pa[4][4];
        #pragma unroll
        for (int j = 0; j < 8; ++j) {
            const int sh = 8*(j & 3);
            const unsigned mlo = ((j < 4) ? ua : ub) >> sh;
            const unsigned mhi = ((j < 4) ? va : vb) >> sh;
            float e0 = (mlo & 1u) ? ex2f(S[j][0]) : 0.f;
            float e1 = (mlo & 2u) ? ex2f(S[j][1]) : 0.f;
            float e2 = (mhi & 1u) ? ex2f(S[j][2]) : 0.f;
            float e3 = (mhi & 2u) ? ex2f(S[j][3]) : 0.f;
            lsum_lo += e0 + e1;
            lsum_hi += e2 + e3;
            Pa[j >> 1][(j & 1)*2 + 0] = packh2(e0, e1);
            Pa[j >> 1][(j & 1)*2 + 1] = packh2(e2, e3);
        }

        // ---- O += P @ V : 8 d-frags, B-frags via ldmatrix.x4
        #pragma unroll
        for (int j = 0; j < 8; ++j) {
            uint32_t a0 = vaddr + j*(16*SH);
            uint32_t b0, b1, b2, b3, b4, b5, b6, b7;
            LDSM_X4(b0, b1, b2, b3, a0);
            LDSM_X4(b4, b5, b6, b7, a0 + 64);
            mma16(O[j], Pa[0], b0, b1);
            mma16(O[j], Pa[1], b2, b3);
            mma16(O[j], Pa[2], b4, b5);
            mma16(O[j], Pa[3], b6, b7);
        }
    }

    // ---- normalize + write fp16
    lsum_lo += __shfl_xor_sync(0xffffffffu, lsum_lo, 1);
    lsum_lo += __shfl_xor_sync(0xffffffffu, lsum_lo, 2);
    lsum_hi += __shfl_xor_sync(0xffffffffu, lsum_hi, 1);
    lsum_hi += __shfl_xor_sync(0xffffffffu, lsum_hi, 2);
    const float il = 1.f / lsum_lo;
    const float ih = 1.f / lsum_hi;

    uint32_t* o0 = (uint32_t*)g_atth + (size_t)(n*LSEQ + r0)*(EMB/2) + h*(HD/2);
    uint32_t* o1 = o0 + (size_t)8*(EMB/2);
    #pragma unroll
    for (int j = 0; j < 8; ++j) {
        o0[4*j + t] = packh2(O[j][0]*il, O[j][1]*il);
        o1[4*j + t] = packh2(O[j][2]*ih, O[j][3]*ih);
    }
}

// ---------------------------------------------------------------------------
// Kernel 4: out = att @ Wo^T + bo, fp16 mma, 128x128 tile, K-chunk 64,
// double-buffered cp.async from g_atth / g_woh. Dynamic smem 73728 B.
// ---------------------------------------------------------------------------
#define OPBUFH 18432   // halves per stage (A 9216 + W 9216)

__global__ __launch_bounds__(256) void outproj_mma_kernel(
    const float* __restrict__ bo, float* __restrict__ out)
{
    extern __shared__ unsigned short dsm16[];

    const int o0   = blockIdx.x * 128;
    const int r0b  = blockIdx.y * 128;
    const int tid  = threadIdx.x;
    const int w    = tid >> 5;
    const int lane = tid & 31;
    const int wm   = w >> 1;        // 0..3 (32-row slice)
    const int wn   = w & 1;         // 0..1 (64-col slice)
    const int g    = lane >> 2;
    const int t    = lane & 3;

    auto prefetch = [&](int ch, int b) {
        unsigned short* Ab = dsm16 + b*OPBUFH;
        unsigned short* Wb = Ab + 9216;
        #pragma unroll
        for (int i = tid; i < 1024; i += 256) {
            int r = i >> 3, c8 = (i & 7) << 3;
            cpasync16(smem_u32(&Ab[r*SH + c8]),
                      g_atth + (size_t)(r0b + r)*EMB + ch*64 + c8);
            cpasync16(smem_u32(&Wb[r*SH + c8]),
                      g_woh + (size_t)(o0 + r)*EMB + ch*64 + c8);
        }
    };

    float C[2][8][4];
    #pragma unroll
    for (int m = 0; m < 2; ++m)
        #pragma unroll
        for (int j = 0; j < 8; ++j) { C[m][j][0]=0.f; C[m][j][1]=0.f; C[m][j][2]=0.f; C[m][j][3]=0.f; }

    prefetch(0, 0);
    CP_COMMIT();

    for (int ch = 0; ch < 16; ++ch) {
        const int b = ch & 1;
        __syncthreads();
        prefetch((ch + 1) & 15, b ^ 1);
        CP_COMMIT();
        CP_WAIT1();
        __syncthreads();

        const uint32_t* Au = (const uint32_t*)(dsm16 + b*OPBUFH);
        const uint32_t* Wu = Au + 4608;

        #pragma unroll
        for (int s = 0; s < 4; ++s) {
            uint32_t Aa0[4], Aa1[4];
            const int a0w = (32*wm      + g)*36 + 8*s + t;
            const int a1w = (32*wm + 16 + g)*36 + 8*s + t;
            Aa0[0] = Au[a0w];
            Aa0[1] = Au[a0w + 8*36];
            Aa0[2] = Au[a0w + 4];
            Aa0[3] = Au[a0w + 8*36 + 4];
            Aa1[0] = Au[a1w];
            Aa1[1] = Au[a1w + 8*36];
            Aa1[2] = Au[a1w + 4];
            Aa1[3] = Au[a1w + 8*36 + 4];
            #pragma unroll
            for (int j = 0; j < 8; ++j) {
                const int ww = (64*wn + 8*j + g)*36 + 8*s + t;
                uint32_t b0 = Wu[ww], b1 = Wu[ww + 4];
                mma16(C[0][j], Aa0, b0, b1);
                mma16(C[1][j], Aa1, b0, b1);
            }
        }
    }

    #pragma unroll
    for (int m = 0; m < 2; ++m) {
        const int row0 = r0b + 32*wm + 16*m + g;
        #pragma unroll
        for (int j = 0; j < 8; ++j) {
            int col = o0 + 64*wn + 8*j + 2*t;
            float2 bb = *(const float2*)&bo[col];
            *(float2*)&out[(size_t)row0*EMB + col] =
                make_float2(C[m][j][0] + bb.x, C[m][j][1] + bb.y);
            *(float2*)&out[(size_t)(row0+8)*EMB + col] =
                make_float2(C[m][j][2] + bb.x, C[m][j][3] + bb.y);
        }
    }
}

// ---------------------------------------------------------------------------
extern "C" void kernel_launch(void* const* d_in, const int* in_sizes, int n_in,
                              void* d_out, int out_size)
{
    (void)in_sizes; (void)n_in; (void)out_size;
    const float* vals = (const float*)d_in[0];
    const float* keys = (const float*)d_in[1];
    const float* quer = (const float*)d_in[2];
    const int*   mask = (const int*)  d_in[3];
    const float* Wv   = (const float*)d_in[4];
    const float* Wk   = (const float*)d_in[5];
    const float* Wq   = (const float*)d_in[6];
    const float* Wo   = (const float*)d_in[7];
    const float* bo   = (const float*)d_in[8];
    float* out = (float*)d_out;

    cudaFuncSetAttribute(outproj_mma_kernel,
                         cudaFuncAttributeMaxDynamicSharedMemorySize, 2*OPBUFH*2);

    proj_kernel      <<<dim3(LSEQ/64, HEADS, NB), 256>>>(vals, keys, quer, Wv, Wk, Wq);
    maskpack_kernel  <<<NB*LSEQ, 256>>>(mask);
    wo_half_kernel   <<<EMB*EMB/1024, 256>>>(Wo);
    attn_mma_kernel  <<<dim3(LSEQ/128, HEADS, NB), 256>>>();
    outproj_mma_kernel<<<dim3(EMB/128, NB*LSEQ/128), 256, 2*OPBUFH*2>>>(bo, out);
}